// round 11
// baseline (speedup 1.0000x reference)
#include <cuda_runtime.h>
#include <math.h>

#define NC 1000
#define NA 64

// Scratch. __device__ globals (no allocation allowed).
__device__ float g_pp[1024];
__device__ float g_som[128];

// Kernel 1: blocks 0..124: pp[row] = sum_k W[row,k]*P[row,k] (warp per row).
//           block 125:     omega table g_som[j] = j exact float steps of
//                          (cur -= 0.01f) — predicated FADD chain, free under
//                          the other blocks' DRAM time.
__global__ void pp_kernel(const float* __restrict__ W, const float* __restrict__ P,
                          const float* __restrict__ omega) {
    if (blockIdx.x == 125) {
        int t = threadIdx.x;
        if (t < 128) {
            float w0 = omega[0];
            w0 = fminf(fmaxf(w0, 0.0f), 1.0f);
            float cur = w0;
            #pragma unroll
            for (int k = 0; k < 127; ++k)
                if (k < t) cur -= 0.01f;     // exact float recurrence
            g_som[t] = cur;
        }
        return;
    }
    int warp = (blockIdx.x * blockDim.x + threadIdx.x) >> 5;
    int lane = threadIdx.x & 31;
    if (warp >= NC) return;
    const float2* w2 = reinterpret_cast<const float2*>(W + warp * NA);
    const float2* p2 = reinterpret_cast<const float2*>(P + warp * NA);
    float2 w = w2[lane];
    float2 p = p2[lane];
    float s = w.x * p.x + w.y * p.y;
    #pragma unroll
    for (int off = 16; off; off >>= 1)
        s += __shfl_down_sync(0xffffffffu, s, off);
    if (lane == 0) g_pp[warp] = s;
}

// Kernel 2: 1024-thread solver, TWO barriers total.
//   Phase A: fused argmax(p0) (carrying pp[c]) + sum(exp(pp)); 1 barrier.
//   Local:   per-class exact stop index t_j = analytic window start (theta_j)
//            + 5-point EXACT float check against the omega table; no sync.
//   Phase B: istar = max_j t_j (int max); 1 barrier.  omstar = som[istar].
__global__ __launch_bounds__(1024) void solve_kernel(const float* __restrict__ p0,
                                                     float* __restrict__ out) {
    __shared__ float a_sum[32], a_pv[32], a_pw[32];
    __shared__ int   a_pi[32];
    __shared__ int   b_t[32];
    __shared__ unsigned s_ball[4];
    __shared__ float som[128];

    const unsigned FULL = 0xffffffffu;
    int tid  = threadIdx.x;
    int lane = tid & 31;
    int wid  = tid >> 5;
    bool live = (tid < NC);

    // ---- Early independent loads ----
    if (tid < 128) {
        float v = g_som[tid];
        som[tid] = v;
        unsigned b = __ballot_sync(FULL, (v - 0.01f) < 0.001f);
        if (lane == 0) s_ball[wid] = b;
    }
    float p0v = live ? p0[tid]   : -INFINITY;
    float ppv = live ? g_pp[tid] : 0.0f;

    // ---- Phase A (fused): argmax(p0) carrying pp[c]  +  sum(exp(pp)) ----
    // pp in [-~0.3, ~0.3] => exp perfectly conditioned without max-subtract.
    float e  = live ? __expf(ppv) : 0.0f;
    {
        float ls  = e;
        float lav = p0v;
        int   lai = tid;
        float law = ppv;
        #pragma unroll
        for (int off = 16; off; off >>= 1) {
            ls += __shfl_down_sync(FULL, ls, off);
            float ov = __shfl_down_sync(FULL, lav, off);
            int   oi = __shfl_down_sync(FULL, lai, off);
            float ow = __shfl_down_sync(FULL, law, off);
            if (ov > lav || (ov == lav && oi < lai)) { lav = ov; lai = oi; law = ow; }
        }
        if (lane == 0) { a_sum[wid] = ls; a_pv[wid] = lav; a_pi[wid] = lai; a_pw[wid] = law; }
    }
    __syncthreads();   // barrier 1 (also publishes som / s_ball)

    float sumexp = 0.0f, p0c = -INFINITY, ppc = 0.0f;
    int   c = 0x7fffffff;
    #pragma unroll
    for (int w = 0; w < 32; ++w) {
        sumexp += a_sum[w];                      // fixed order => deterministic
        float ov = a_pv[w]; int oi = a_pi[w];
        if (ov > p0c || (ov == p0c && oi < c)) { p0c = ov; c = oi; ppc = a_pw[w]; }
    }
    float qv = e / sumexp;
    float qc = __expf(ppc) / sumexp;             // bitwise == owner's qv

    float w0 = som[0];
    int nm1 = 127;                               // forced underflow index
    #pragma unroll
    for (int w = 0; w < 4; ++w) {
        unsigned b = s_ball[w];
        if (b) { nm1 = w * 32 + __ffs(b) - 1; break; }
    }

    // ---- Local exact stop index t_j (no sync) ----
    // Violation (j beats c): j<c needs vj >= vc ; j>c needs vj > vc.
    // d(w) = (1-w)A + wB, A = p0c-p0j > 0.  No violation ever if B >= 0 (resp
    // > 0) => t=0.  Else real crossover theta = A/(A-B); float transition lies
    // within +-1 step (margin 0.01*(A-B) >> float noise), so a 5-point exact
    // check starting 2 steps early resolves t exactly.  Cap at nm1 (underflow).
    int t = 0;
    if (live && tid != c) {
        float A = p0c - p0v;
        float B = qc  - qv;
        bool cross = (tid < c) ? (B <= 0.0f) : (B < 0.0f);
        if (cross) {
            float theta = A / (A - B);
            int ie = (int)ceilf((w0 - theta) * 100.0f);
            int s0 = ie - 2;
            if (s0 < 0) s0 = 0;
            if (s0 > nm1) s0 = nm1;
            t = nm1;                             // default: violating to the end
            bool found = false;
            #pragma unroll
            for (int s = 0; s < 5; ++s) {
                int i = s0 + s;
                if (i > nm1) i = nm1;
                float cw   = som[i];
                float onem = 1.0f - cw;
                float vc = onem * p0c + cw * qc;
                float vj = onem * p0v + cw * qv;
                bool viol = (tid < c) ? (vj >= vc) : (vj > vc);
                if (!found && !viol) { t = i; found = true; }
            }
        }
    }

    // ---- Phase B: istar = max_j t_j ----
    {
        int m = t;
        #pragma unroll
        for (int off = 16; off; off >>= 1)
            m = max(m, __shfl_down_sync(FULL, m, off));
        if (lane == 0) b_t[wid] = m;
    }
    __syncthreads();   // barrier 2
    int istar = 0;
    #pragma unroll
    for (int w = 0; w < 32; ++w) istar = max(istar, b_t[w]);

    // ---- Output: p = (1-omega*) * p0 + omega* * q, shape (1, NC) ----
    if (live) {
        float om = som[istar];                   // uniform broadcast LDS
        out[tid] = (1.0f - om) * p0v + om * qv;
    }
}

extern "C" void kernel_launch(void* const* d_in, const int* in_sizes, int n_in,
                              void* d_out, int out_size) {
    const float* p0 = (const float*)d_in[0];
    const float* P  = (const float*)d_in[1];
    const float* W  = (const float*)d_in[2];
    const float* om = (const float*)d_in[3];
    float* out = (float*)d_out;

    pp_kernel<<<126, 256>>>(W, P, om);
    solve_kernel<<<1, 1024>>>(p0, out);
}

// round 12
// speedup vs baseline: 1.0218x; 1.0218x over previous
#include <cuda_runtime.h>
#include <math.h>

#define NC   1000
#define NA   64
#define NBLK 33          // 32 pp blocks + 1 omega block

// Scratch + arrival counter. __device__ globals (no allocation allowed).
// g_count self-resets (last block zeroes it) => graph replays work.
__device__ float g_pp[1024];
__device__ float g_som[128];
__device__ int   g_count = 0;

// Single fused kernel, one wave (33 blocks <= 148 SMs), no spinning:
//   blocks 0..31 : pp[row] = sum_k W[row,k]*P[row,k], one warp per row.
//   block 32     : omega table g_som[j] = j exact float steps of (cur -= 0.01f).
//   every block  : prefetches p0 into registers BEFORE arrival.
//   last arrival : runs the lean 2-barrier solver (1024 threads).
__global__ __launch_bounds__(1024) void fused_kernel(const float* __restrict__ p0,
                                                     const float* __restrict__ P,
                                                     const float* __restrict__ W,
                                                     const float* __restrict__ omega,
                                                     float* __restrict__ out) {
    __shared__ int   s_last;
    __shared__ float a_sum[32], a_pv[32], a_pw[32];
    __shared__ int   a_pi[32];
    __shared__ int   b_t[32];
    __shared__ unsigned s_ball[4];
    __shared__ float som[128];

    const unsigned FULL = 0xffffffffu;
    int tid  = threadIdx.x;
    int lane = tid & 31;
    int wid  = tid >> 5;
    bool live = (tid < NC);

    // ---- prefetch p0 (every block) so the solver already holds it ----
    float p0v = live ? p0[tid] : -INFINITY;

    // ---- Phase 1: producer work ----
    if (blockIdx.x == 32) {
        // omega table: thread j -> omega_j via exact float recurrence
        // (predicated unrolled FADD chain, no branches)
        if (tid < 128) {
            float w0 = omega[0];
            w0 = fminf(fmaxf(w0, 0.0f), 1.0f);
            float cur = w0;
            #pragma unroll
            for (int k = 0; k < 127; ++k)
                if (k < tid) cur -= 0.01f;
            g_som[tid] = cur;
        }
    } else {
        int row = blockIdx.x * 32 + wid;     // warp per row
        if (row < NC) {
            const float2* w2 = reinterpret_cast<const float2*>(W + row * NA);
            const float2* p2 = reinterpret_cast<const float2*>(P + row * NA);
            float2 w = w2[lane];
            float2 p = p2[lane];
            float s = w.x * p.x + w.y * p.y;
            #pragma unroll
            for (int off = 16; off; off >>= 1)
                s += __shfl_down_sync(FULL, s, off);
            if (lane == 0) g_pp[row] = s;
        }
    }
    __syncthreads();

    // ---- Arrival: elect the last block (no spinning; single wave) ----
    if (tid == 0) {
        __threadfence();                     // release producer writes
        int old = atomicAdd(&g_count, 1);
        int last = (old == NBLK - 1);
        s_last = last;
        if (last) g_count = 0;               // reset for next graph replay
    }
    __syncthreads();
    if (!s_last) return;
    __threadfence();                         // acquire before reading g_pp/g_som

    // ================= Lean 2-barrier solver =================
    if (tid < 128) {
        float v = __ldcg(&g_som[tid]);
        som[tid] = v;
        unsigned b = __ballot_sync(FULL, (v - 0.01f) < 0.001f);
        if (lane == 0) s_ball[wid] = b;
    }
    float ppv = live ? __ldcg(&g_pp[tid]) : 0.0f;

    // ---- Phase A (fused): argmax(p0) carrying pp[c]  +  sum(exp(pp)) ----
    // pp in [~-0.3, 0.3] => exp perfectly conditioned without max-subtract.
    float e = live ? __expf(ppv) : 0.0f;
    {
        float ls  = e;
        float lav = p0v;
        int   lai = tid;
        float law = ppv;
        #pragma unroll
        for (int off = 16; off; off >>= 1) {
            ls += __shfl_down_sync(FULL, ls, off);
            float ov = __shfl_down_sync(FULL, lav, off);
            int   oi = __shfl_down_sync(FULL, lai, off);
            float ow = __shfl_down_sync(FULL, law, off);
            if (ov > lav || (ov == lav && oi < lai)) { lav = ov; lai = oi; law = ow; }
        }
        if (lane == 0) { a_sum[wid] = ls; a_pv[wid] = lav; a_pi[wid] = lai; a_pw[wid] = law; }
    }
    __syncthreads();   // barrier 1 (also publishes som / s_ball)

    float sumexp = 0.0f, p0c = -INFINITY, ppc = 0.0f;
    int   c = 0x7fffffff;
    #pragma unroll
    for (int w = 0; w < 32; ++w) {
        sumexp += a_sum[w];                  // fixed order => deterministic
        float ov = a_pv[w]; int oi = a_pi[w];
        if (ov > p0c || (ov == p0c && oi < c)) { p0c = ov; c = oi; ppc = a_pw[w]; }
    }
    float qv = e / sumexp;
    float qc = __expf(ppc) / sumexp;         // bitwise == owner's qv

    float w0 = som[0];
    int nm1 = 127;                           // forced underflow index
    #pragma unroll
    for (int w = 0; w < 4; ++w) {
        unsigned b = s_ball[w];
        if (b) { nm1 = w * 32 + __ffs(b) - 1; break; }
    }

    // ---- Local exact stop index t_j (no sync) ----
    // Violation (j beats c): j<c needs vj >= vc ; j>c needs vj > vc.
    // d(w) = (1-w)A + wB, A = p0c-p0j > 0.  No crossover => t=0.  Else real
    // crossover theta = A/(A-B); the float transition lies within +-1 step
    // (margin 0.01*(A-B) >> float noise) so a 5-point exact check starting
    // 2 steps early resolves t exactly.  Capped at nm1 (underflow).
    int t = 0;
    if (live && tid != c) {
        float A = p0c - p0v;
        float B = qc  - qv;
        bool cross = (tid < c) ? (B <= 0.0f) : (B < 0.0f);
        if (cross) {
            float theta = A / (A - B);
            int ie = (int)ceilf((w0 - theta) * 100.0f);
            int s0 = ie - 2;
            if (s0 < 0) s0 = 0;
            if (s0 > nm1) s0 = nm1;
            t = nm1;                         // default: violating to the end
            bool found = false;
            #pragma unroll
            for (int s = 0; s < 5; ++s) {
                int i = s0 + s;
                if (i > nm1) i = nm1;
                float cw   = som[i];
                float onem = 1.0f - cw;
                float vc = onem * p0c + cw * qc;
                float vj = onem * p0v + cw * qv;
                bool viol = (tid < c) ? (vj >= vc) : (vj > vc);
                if (!found && !viol) { t = i; found = true; }
            }
        }
    }

    // ---- Phase B: istar = max_j t_j (REDUX + one barrier) ----
    {
        int m = __reduce_max_sync(FULL, t);
        if (lane == 0) b_t[wid] = m;
    }
    __syncthreads();   // barrier 2
    int istar = 0;
    #pragma unroll
    for (int w = 0; w < 32; ++w) istar = max(istar, b_t[w]);

    // ---- Output: p = (1-omega*) * p0 + omega* * q, shape (1, NC) ----
    if (live) {
        float om = som[istar];               // uniform broadcast LDS
        out[tid] = (1.0f - om) * p0v + om * qv;
    }
}

extern "C" void kernel_launch(void* const* d_in, const int* in_sizes, int n_in,
                              void* d_out, int out_size) {
    const float* p0 = (const float*)d_in[0];
    const float* P  = (const float*)d_in[1];
    const float* W  = (const float*)d_in[2];
    const float* om = (const float*)d_in[3];
    float* out = (float*)d_out;

    fused_kernel<<<NBLK, 1024>>>(p0, P, W, om, out);
}

// round 13
// speedup vs baseline: 1.2285x; 1.2022x over previous
#include <cuda_runtime.h>
#include <math.h>

#define NC 1000
#define NA 64

// Scratch. __device__ globals (no allocation allowed).
__device__ float g_pp[1024];
__device__ float g_som[128];

// Kernel 1: blocks 0..124: pp[row] = sum_k W[row,k]*P[row,k] (warp per row).
//           block 125:     omega table g_som[j] = j exact float steps of
//                          (cur -= 0.01f) — predicated FADD chain, free under
//                          the other blocks' DRAM time.
__global__ void pp_kernel(const float* __restrict__ W, const float* __restrict__ P,
                          const float* __restrict__ omega) {
    if (blockIdx.x == 125) {
        int t = threadIdx.x;
        if (t < 128) {
            float w0 = omega[0];
            w0 = fminf(fmaxf(w0, 0.0f), 1.0f);
            float cur = w0;
            #pragma unroll
            for (int k = 0; k < 127; ++k)
                if (k < t) cur -= 0.01f;     // exact float recurrence
            g_som[t] = cur;
        }
        return;
    }
    int warp = (blockIdx.x * blockDim.x + threadIdx.x) >> 5;
    int lane = threadIdx.x & 31;
    if (warp >= NC) return;
    const float2* w2 = reinterpret_cast<const float2*>(W + warp * NA);
    const float2* p2 = reinterpret_cast<const float2*>(P + warp * NA);
    float2 w = w2[lane];
    float2 p = p2[lane];
    float s = w.x * p.x + w.y * p.y;
    #pragma unroll
    for (int off = 16; off; off >>= 1)
        s += __shfl_down_sync(0xffffffffu, s, off);
    if (lane == 0) g_pp[warp] = s;
}

// Kernel 2: issue-lean 1024-thread solver.
//   Block is ISSUE-bound (4 slots/cyc): minimize total instructions x warps.
//   All block-level reductions are TWO-STAGE with stage 2 on warp 0 ONLY
//   (a flat 32-entry combine by all warps costs ~2400 issue cycles; stage-2
//   on one warp costs ~30).  Algorithm: fused argmax(p0)+sum(exp(pp)) ->
//   local per-class exact stop index t_j (analytic crossover + 5-point exact
//   float check) -> istar = max t_j -> blend.
__global__ __launch_bounds__(1024) void solve_kernel(const float* __restrict__ p0,
                                                     float* __restrict__ out) {
    __shared__ float a_sum[32], a_pv[32], a_pw[32];
    __shared__ int   a_pi[32];
    __shared__ int   b_t[32];
    __shared__ unsigned s_ball[4];
    __shared__ float som[128];
    __shared__ float s_sumexp, s_p0c, s_ppc;
    __shared__ int   s_c, s_istar;

    const unsigned FULL = 0xffffffffu;
    int tid  = threadIdx.x;
    int lane = tid & 31;
    int wid  = tid >> 5;
    bool live = (tid < NC);

    // ---- Early independent loads ----
    if (tid < 128) {
        float v = g_som[tid];
        som[tid] = v;
        unsigned b = __ballot_sync(FULL, (v - 0.01f) < 0.001f);
        if (lane == 0) s_ball[wid] = b;
    }
    float p0v = live ? p0[tid]   : -INFINITY;
    float ppv = live ? g_pp[tid] : 0.0f;

    // ---- Phase A: warp tree for { sum(exp(pp)), argmax(p0) carrying pp } ----
    // pp in [~-0.3, 0.3] => exp perfectly conditioned without max-subtract.
    float e = live ? __expf(ppv) : 0.0f;
    {
        float ls  = e;
        float lav = p0v;
        int   lai = tid;
        float law = ppv;
        #pragma unroll
        for (int off = 16; off; off >>= 1) {
            ls += __shfl_down_sync(FULL, ls, off);
            float ov = __shfl_down_sync(FULL, lav, off);
            int   oi = __shfl_down_sync(FULL, lai, off);
            float ow = __shfl_down_sync(FULL, law, off);
            if (ov > lav || (ov == lav && oi < lai)) { lav = ov; lai = oi; law = ow; }
        }
        if (lane == 0) { a_sum[wid] = ls; a_pv[wid] = lav; a_pi[wid] = lai; a_pw[wid] = law; }
    }
    __syncthreads();

    // ---- Phase A stage 2: WARP 0 ONLY ----
    if (wid == 0) {
        float ls  = a_sum[lane];
        float lav = a_pv[lane];
        int   lai = a_pi[lane];
        float law = a_pw[lane];
        #pragma unroll
        for (int off = 16; off; off >>= 1) {
            ls += __shfl_down_sync(FULL, ls, off);
            float ov = __shfl_down_sync(FULL, lav, off);
            int   oi = __shfl_down_sync(FULL, lai, off);
            float ow = __shfl_down_sync(FULL, law, off);
            if (ov > lav || (ov == lav && oi < lai)) { lav = ov; lai = oi; law = ow; }
        }
        if (lane == 0) { s_sumexp = ls; s_p0c = lav; s_c = lai; s_ppc = law; }
    }
    __syncthreads();

    float sumexp = s_sumexp;
    float p0c    = s_p0c;
    int   c      = s_c;
    float qv = e / sumexp;
    float qc = __expf(s_ppc) / sumexp;        // bitwise == owner's qv

    // nm1 (forced underflow index) from ballots — cheap, redundant (~12 instr)
    float w0 = som[0];
    int nm1 = 127;
    #pragma unroll
    for (int w = 0; w < 4; ++w) {
        unsigned b = s_ball[w];
        if (b) { nm1 = w * 32 + __ffs(b) - 1; break; }
    }

    // ---- Local exact stop index t_j (no sync) ----
    // Violation (j beats c): j<c needs vj >= vc ; j>c needs vj > vc.
    // d(w) = (1-w)A + wB, A = p0c-p0j > 0.  No crossover => t=0.  Else real
    // crossover theta = A/(A-B); float transition lies within +-1 step
    // (margin 0.01*(A-B) >> float noise): 5-point exact check starting 2
    // steps early resolves t exactly.  Capped at nm1 (underflow).
    int t = 0;
    if (live && tid != c) {
        float A = p0c - p0v;
        float B = qc  - qv;
        bool cross = (tid < c) ? (B <= 0.0f) : (B < 0.0f);
        if (cross) {
            float theta = A / (A - B);
            int ie = (int)ceilf((w0 - theta) * 100.0f);
            int s0 = ie - 2;
            if (s0 < 0) s0 = 0;
            if (s0 > nm1) s0 = nm1;
            t = nm1;                          // default: violating to the end
            bool found = false;
            #pragma unroll
            for (int s = 0; s < 5; ++s) {
                int i = s0 + s;
                if (i > nm1) i = nm1;
                float cw   = som[i];
                float onem = 1.0f - cw;
                float vc = onem * p0c + cw * qc;
                float vj = onem * p0v + cw * qv;
                bool viol = (tid < c) ? (vj >= vc) : (vj > vc);
                if (!found && !viol) { t = i; found = true; }
            }
        }
    }

    // ---- Phase B: istar = max t  (REDUX per warp; stage 2 on warp 0) ----
    {
        int m = __reduce_max_sync(FULL, t);
        if (lane == 0) b_t[wid] = m;
    }
    __syncthreads();
    if (wid == 0) {
        int m = __reduce_max_sync(FULL, b_t[lane]);
        if (lane == 0) s_istar = m;
    }
    __syncthreads();

    // ---- Output: p = (1-omega*) * p0 + omega* * q, shape (1, NC) ----
    if (live) {
        float om = som[s_istar];              // uniform broadcast LDS
        out[tid] = (1.0f - om) * p0v + om * qv;
    }
}

extern "C" void kernel_launch(void* const* d_in, const int* in_sizes, int n_in,
                              void* d_out, int out_size) {
    const float* p0 = (const float*)d_in[0];
    const float* P  = (const float*)d_in[1];
    const float* W  = (const float*)d_in[2];
    const float* om = (const float*)d_in[3];
    float* out = (float*)d_out;

    pp_kernel<<<126, 256>>>(W, P, om);
    solve_kernel<<<1, 1024>>>(p0, out);
}